// round 15
// baseline (speedup 1.0000x reference)
#include <cuda_runtime.h>
#include <math.h>

#define NATOMS 65536
#define NM     6
#define LL     7
#define NC     (NM*LL*LL)   // 294
#define RCF    6.0f
#define RCINV  (1.0f/6.0f)

// pass1: 2 threads per atom, 64 atoms per 128-thread block
#define TPB1   128
#define APB    64
#define NBLK1  (NATOMS/APB)   // 1024

// pass2: 1 atom per thread, 128 atoms per block; grid doubled by l-split
#define TPB2   128
#define NBLK2  (NATOMS/TPB2)  // 512 atom-blocks; launch 2*NBLK2
#define BUF_BYTES (21*TPB2*3*4)   // one stage buffer: 32256 B

__device__ float g_part[NBLK1 * NC];
__device__ float g_c[NC];

// ---------------------------------------------------------------------------
// Value-row recursion step: dest holds row lv-2, overwritten in place.
// ---------------------------------------------------------------------------
#define V_STEP(lv, RS, IS, RD, ID) do {                                        \
    _Pragma("unroll")                                                          \
    for (int m = 0; m < lv-1; m++){                                            \
        const float invA =                                                     \
            rsqrtf((float)(lv*lv - m*m)/((2.0f*lv-1.0f)*(2.0f*lv+1.0f)));      \
        const float Ap = sqrtf((float)((lv-1)*(lv-1) - m*m)/                   \
                               ((2.0f*lv-3.0f)*(2.0f*lv-1.0f)));               \
        const float o_r = RD[m], o_i = ID[m];                                  \
        RD[m] = (z*RS[m] - Ap*r2*o_r)*invA;                                    \
        ID[m] = (z*IS[m] - Ap*r2*o_i)*invA;                                    \
    }                                                                          \
    {   const int m = lv-1;                                                    \
        const float invA =                                                     \
            rsqrtf((float)(lv*lv - m*m)/((2.0f*lv-1.0f)*(2.0f*lv+1.0f)));      \
        RD[m] = z*RS[m]*invA;                                                  \
        ID[m] = z*IS[m]*invA;                                                  \
    }                                                                          \
    {   const float alc = -sqrtf((2.0f*lv + 1.0f)/(2.0f*lv));                  \
        RD[lv] = alc*(x*RS[lv-1] - y*IS[lv-1]);                                \
        ID[lv] = alc*(x*IS[lv-1] + y*RS[lv-1]);                                \
    }                                                                          \
} while(0)

// ---------------------------------------------------------------------------
// Pass 1: values-only recursion; single-stage warp reduction (16 partials).
// ---------------------------------------------------------------------------
#define P1_RED(val, idx) do {                                                  \
    float _v = (val);                                                          \
    _v += __shfl_xor_sync(0xffffffffu, _v, 16);                                \
    if (lane < 16) wsh[wloc][lane][idx] = _v;                                  \
} while(0)

#define V_EMIT(lv, RD, ID) do {                                                \
    _Pragma("unroll")                                                          \
    for (int m = 0; m <= lv; m++){                                             \
        const float yv = RD[m];                                                \
        _Pragma("unroll")                                                      \
        for (int bb = 0; bb < 3; bb++)                                         \
            P1_RED(fh[bb]*yv, vb + bb*49 + lv*7 + (lv-m));                     \
    }                                                                          \
    _Pragma("unroll")                                                          \
    for (int m = 1; m <= lv; m++){                                             \
        const float yv = ID[m];                                                \
        _Pragma("unroll")                                                      \
        for (int bb = 0; bb < 3; bb++)                                         \
            P1_RED(fh[bb]*yv, vb + bb*49 + (m-1)*7 + lv);                      \
    }                                                                          \
} while(0)

__global__ void __launch_bounds__(TPB1) pass1(const float* __restrict__ xyz){
    __shared__ float wsh[2][16][NC];
    const int t    = threadIdx.x;
    const int lane = t & 31;
    const int half = t >> 6;
    const int al   = t & 63;
    const int wloc = al >> 5;
    const int vb   = half*3*49;
    const int j = blockIdx.x * APB + al;

    const float x = xyz[3*j+0], y = xyz[3*j+1], z = xyz[3*j+2];
    const float r2 = x*x + y*y + z*z;
    const float d  = sqrtf(r2);
    const float tc = 1.0f - d*RCINV;
    const float rcut = (d < RCF) ? tc*tc : 0.0f;

    float fh[3];
    {
        const float r6 = r2*r2*r2;
        fh[0] = rcut * (half ? r6 : 1.0f);
        fh[1] = fh[0]*r2;
        fh[2] = fh[1]*r2;
    }

    float RA[LL], IA[LL], RB[LL], IB[LL];
    RA[0] = 0.28209479177387814f; IA[0] = 0.0f;
    V_EMIT(0, RA, IA);
    {
        const float sq3 = 1.7320508075688772f;
        RB[0] = z*RA[0]*sq3;
        IB[0] = 0.0f;
        const float alc = -1.2247448713915890f;
        RB[1] = alc*(x*RA[0]);
        IB[1] = alc*(y*RA[0]);
    }
    V_EMIT(1, RB, IB);
    V_STEP(2, RB, IB, RA, IA); V_EMIT(2, RA, IA);
    V_STEP(3, RA, IA, RB, IB); V_EMIT(3, RB, IB);
    V_STEP(4, RB, IB, RA, IA); V_EMIT(4, RA, IA);
    V_STEP(5, RA, IA, RB, IB); V_EMIT(5, RB, IB);
    V_STEP(6, RB, IB, RA, IA); V_EMIT(6, RA, IA);

    __syncthreads();
    for (int v = t; v < NC; v += TPB1){
        float s = 0.0f;
        #pragma unroll
        for (int w = 0; w < 2; w++)
            #pragma unroll
            for (int c = 0; c < 16; c++)
                s += wsh[w][c][v];
        g_part[blockIdx.x*NC + v] = s;
    }
}

// ---------------------------------------------------------------------------
// Stage-1 reduce: one block per c-channel; 256 threads sum 1024 partials.
// ---------------------------------------------------------------------------
__global__ void __launch_bounds__(256) reduce_part(){
    const int v = blockIdx.x;
    const int t = threadIdx.x;
    float s = 0.0f;
    #pragma unroll
    for (int k = 0; k < NBLK1/256; k++)
        s += g_part[(t + k*256)*NC + v];
    s += __shfl_xor_sync(0xffffffffu, s, 16);
    s += __shfl_xor_sync(0xffffffffu, s, 8);
    s += __shfl_xor_sync(0xffffffffu, s, 4);
    s += __shfl_xor_sync(0xffffffffu, s, 2);
    s += __shfl_xor_sync(0xffffffffu, s, 1);
    __shared__ float sm[8];
    if ((t & 31) == 0) sm[t >> 5] = s;
    __syncthreads();
    if (t == 0){
        float r = 0.0f;
        #pragma unroll
        for (int w = 0; w < 8; w++) r += sm[w];
        g_c[v] = r;
    }
}

// ---------------------------------------------------------------------------
// Stage-2: compute p (first 252 outputs) from g_c. One small block.
// ---------------------------------------------------------------------------
__global__ void __launch_bounds__(256) finalize_p(float* __restrict__ out){
    __shared__ float csh[NC];
    const int t = threadIdx.x;
    for (int i = t; i < NC; i += 256) csh[i] = g_c[i];
    __syncthreads();
    if (t < LL*NM*NM){   // 252
        const int l = t / 36;
        const int a = (t / 6) % 6;
        const int b = t % 6;
        const float* ca = &csh[a*49];
        const float* cb = &csh[b*49];
        float s = 0.0f;
        for (int m = 0; m <= l; m++){
            const float w = (m == l) ? 1.0f : 2.0f;
            s += w * ca[l*7 + m] * cb[l*7 + m];
        }
        for (int lp = 0; lp < l; lp++){
            s += 2.0f * ca[lp*7 + l] * cb[lp*7 + l];
        }
        out[t] = s;
    }
}

// ---------------------------------------------------------------------------
// Pass 2: values-only ping-pong recursion; gradients synthesized from row l-1;
// DOUBLE-BUFFERED smem staging -> cp.async.bulk stores. The copy of emit k
// overlaps the entire emit k+1 (G/H compute + staging into the other buffer).
// Grid doubled by l-split: group 0 emits l in {0,5,6}; group 1 l in {1,2,3,4}.
// ---------------------------------------------------------------------------
__device__ __forceinline__ int pair_idx(int a, int b){
    return a*6 - (a*(a+1))/2 + b;
}

#define LGRP(lv) ((lv)==0 || (lv)==5 || (lv)==6 ? 0 : 1)

#define D_EMIT(lv, CR, CI, PR, PI) if (grp == LGRP(lv)) {                      \
    float G[6]={0,0,0,0,0,0}, Hx[6]={0,0,0,0,0,0},                             \
          Hy[6]={0,0,0,0,0,0}, Hz[6]={0,0,0,0,0,0};                            \
    _Pragma("unroll")                                                          \
    for (int m = 0; m <= lv; m++){                                             \
        const float az  = (m <= lv-1)                                          \
            ? sqrtf((float)((lv-m)*(lv+m))*(2.0f*lv+1.0f)/(2.0f*lv-1.0f))      \
            : 0.0f;                                                            \
        const float apH = (m+1 <= lv-1)                                        \
            ? 0.5f*sqrtf((float)((lv-m)*(lv-m-1))*(2.0f*lv+1.0f)/(2.0f*lv-1.0f))\
            : 0.0f;                                                            \
        const float amH = (lv >= 1 && (m >= 1 || lv >= 2))                     \
            ? 0.5f*sqrtf((float)((lv+m)*(lv+m-1))*(2.0f*lv+1.0f)/(2.0f*lv-1.0f))\
            : 0.0f;                                                            \
        const float prp = (m+1 <= lv-1) ? PR[m+1] : 0.0f;                      \
        const float pip = (m+1 <= lv-1) ? PI[m+1] : 0.0f;                      \
        const float prm = (m >= 1) ? PR[m-1] : ((lv >= 2) ? -PR[1] : 0.0f);    \
        const float pim = (m >= 1) ? PI[m-1] : ((lv >= 2) ?  PI[1] : 0.0f);    \
        const float pzr = (m <= lv-1) ? PR[m] : 0.0f;                          \
        const float pzi = (m <= lv-1) ? PI[m] : 0.0f;                          \
        const float gzr = az*pzr,                 gzi = az*pzi;                \
        const float gxr = apH*prp - amH*prm,      gxi = apH*pip - amH*pim;     \
        const float gyr = apH*pip + amH*pim,      gyi = -(apH*prp + amH*prm);  \
        const float w = (m == 0) ? 1.0f : 2.0f;                                \
        _Pragma("unroll")                                                      \
        for (int b = 0; b < 6; b++){                                           \
            const float wr = w * csh[b*49 + lv*7 + (lv - m)];                  \
            G[b]  += wr*CR[m]; Hx[b] += wr*gxr;                                \
            Hy[b] += wr*gyr;   Hz[b] += wr*gzr;                                \
        }                                                                      \
        if (m >= 1){                                                           \
            _Pragma("unroll")                                                  \
            for (int b = 0; b < 6; b++){                                       \
                const float wi = 2.0f * csh[b*49 + (m-1)*7 + lv];              \
                G[b]  += wi*CI[m]; Hx[b] += wi*gxi;                            \
                Hy[b] += wi*gyi;   Hz[b] += wi*gzi;                            \
            }                                                                  \
        }                                                                      \
    }                                                                          \
    /* allow 1 in-flight copy (it reads the OTHER buffer) */                   \
    if (t < 36)                                                                \
        asm volatile("cp.async.bulk.wait_group.read 1;" ::: "memory");         \
    __syncthreads();                                                           \
    /* stage 21 unique pairs into stage[ebuf] */                               \
    float pa = 1.0f;                                                           \
    _Pragma("unroll")                                                          \
    for (int a = 0; a < 6; a++){                                               \
        const float fa  = rcut*pa;                                             \
        const float dca = pa*(drc + (2.0f*a)*rcut*invd);                       \
        float pb = pa;                                                         \
        _Pragma("unroll")                                                      \
        for (int b = a; b < 6; b++){                                           \
            const float fb  = rcut*pb;                                         \
            const float dcb = pb*(drc + (2.0f*b)*rcut*invd);                   \
            const float s  = dca*G[b] + dcb*G[a];                              \
            float* sp = &stage[ebuf][pair_idx(a,b)][3*t];                      \
            sp[0] = ux*s + fa*Hx[b] + fb*Hx[a];                                \
            sp[1] = uy*s + fa*Hy[b] + fb*Hy[a];                                \
            sp[2] = uz*s + fa*Hz[b] + fb*Hz[a];                                \
            pb *= r2;                                                          \
        }                                                                      \
        pa *= r2;                                                              \
    }                                                                          \
    __syncthreads();                                                           \
    /* one async bulk copy per output stream (1536 B contiguous) */            \
    if (t < 36){                                                               \
        asm volatile("fence.proxy.async.shared::cta;" ::: "memory");           \
        const int a = t / 6, b2 = t % 6;                                       \
        const int p = (a <= b2) ? pair_idx(a,b2) : pair_idx(b2,a);             \
        const unsigned src = stage_u32 + (unsigned)(ebuf*BUF_BYTES + p*(TPB2*3*4)); \
        float* dst = out + 252 + (size_t)(lv*36 + t)*stride                    \
                   + (size_t)ablk*(TPB2*3);                                    \
        asm volatile(                                                          \
            "cp.async.bulk.global.shared::cta.bulk_group [%0], [%1], %2;"      \
            :: "l"(dst), "r"(src), "n"(TPB2*3*4) : "memory");                  \
        asm volatile("cp.async.bulk.commit_group;" ::: "memory");              \
    }                                                                          \
    ebuf ^= 1;                                                                 \
}

__global__ void __launch_bounds__(TPB2, 3) pass2(const float* __restrict__ xyz,
                                                 float* __restrict__ out){
    __shared__ __align__(16) float stage[2][21][TPB2*3];
    __shared__ float csh[NC];
    const int t = threadIdx.x;
    const int grp  = blockIdx.x >> 9;          // 0: l in {0,5,6}; 1: l in {1,2,3,4}
    const int ablk = blockIdx.x & (NBLK2-1);   // atom block
    const unsigned stage_u32 = (unsigned)__cvta_generic_to_shared(stage);
    int ebuf = 0;
    for (int i = t; i < NC; i += TPB2) csh[i] = g_c[i];
    __syncthreads();

    const int j = ablk * TPB2 + t;
    const float x = xyz[3*j+0], y = xyz[3*j+1], z = xyz[3*j+2];
    const float r2 = x*x + y*y + z*z;
    const float invd = rsqrtf(r2);
    const float d = r2 * invd;
    const float ux = x*invd, uy = y*invd, uz = z*invd;

    const float tc = 1.0f - d*RCINV;
    const bool  in = (d < RCF);
    const float rcut = in ? tc*tc : 0.0f;
    const float drc  = in ? (-2.0f*RCINV)*tc : 0.0f;

    const size_t stride = (size_t)3 * NATOMS;

    float RA[LL], IA[LL], RB[LL], IB[LL];
    RA[0] = 0.28209479177387814f; IA[0] = 0.0f;
    D_EMIT(0, RA, IA, RB, IB);

    {
        const float sq3 = 1.7320508075688772f;
        RB[0] = z*RA[0]*sq3;
        IB[0] = 0.0f;
        const float alc = -1.2247448713915890f;
        RB[1] = alc*(x*RA[0]);
        IB[1] = alc*(y*RA[0]);
    }
    D_EMIT(1, RB, IB, RA, IA);

    V_STEP(2, RB, IB, RA, IA); D_EMIT(2, RA, IA, RB, IB);
    V_STEP(3, RA, IA, RB, IB); D_EMIT(3, RB, IB, RA, IA);
    V_STEP(4, RB, IB, RA, IA); D_EMIT(4, RA, IA, RB, IB);
    V_STEP(5, RA, IA, RB, IB); D_EMIT(5, RB, IB, RA, IA);
    V_STEP(6, RB, IB, RA, IA); D_EMIT(6, RA, IA, RB, IB);

    // drain outstanding bulk-store groups before exit
    if (t < 36)
        asm volatile("cp.async.bulk.wait_group 0;" ::: "memory");
}

// ---------------------------------------------------------------------------
extern "C" void kernel_launch(void* const* d_in, const int* in_sizes, int n_in,
                              void* d_out, int out_size){
    const float* xyz = (const float*)d_in[0];
    float* out = (float*)d_out;
    pass1<<<NBLK1, TPB1>>>(xyz);
    reduce_part<<<NC, 256>>>();
    finalize_p<<<1, 256>>>(out);
    pass2<<<2*NBLK2, TPB2>>>(xyz, out);
}

// round 16
// speedup vs baseline: 1.1153x; 1.1153x over previous
#include <cuda_runtime.h>
#include <math.h>

#define NATOMS 65536
#define NM     6
#define LL     7
#define NC     (NM*LL*LL)   // 294
#define RCF    6.0f
#define RCINV  (1.0f/6.0f)

// pass1: 2 threads per atom-slot, 2 atoms per thread -> 128 atoms per 128-thread block
#define TPB1   128
#define APB    128
#define NBLK1  (NATOMS/APB)   // 512

// pass2: 1 atom per thread, 128 atoms per block; grid doubled by l-split
#define TPB2   128
#define NBLK2  (NATOMS/TPB2)  // 512 atom-blocks; launch 2*NBLK2

__device__ float g_part[NBLK1 * NC];
__device__ float g_c[NC];

// ---------------------------------------------------------------------------
// Generic value-row recursion step with explicit coords: dest holds row lv-2,
// overwritten in place.
// ---------------------------------------------------------------------------
#define V_STEPG(lv, RS, IS, RD, ID, X, Y, Z, R2) do {                          \
    _Pragma("unroll")                                                          \
    for (int m = 0; m < lv-1; m++){                                            \
        const float invA =                                                     \
            rsqrtf((float)(lv*lv - m*m)/((2.0f*lv-1.0f)*(2.0f*lv+1.0f)));      \
        const float Ap = sqrtf((float)((lv-1)*(lv-1) - m*m)/                   \
                               ((2.0f*lv-3.0f)*(2.0f*lv-1.0f)));               \
        const float o_r = RD[m], o_i = ID[m];                                  \
        RD[m] = ((Z)*RS[m] - Ap*(R2)*o_r)*invA;                                \
        ID[m] = ((Z)*IS[m] - Ap*(R2)*o_i)*invA;                                \
    }                                                                          \
    {   const int m = lv-1;                                                    \
        const float invA =                                                     \
            rsqrtf((float)(lv*lv - m*m)/((2.0f*lv-1.0f)*(2.0f*lv+1.0f)));      \
        RD[m] = (Z)*RS[m]*invA;                                                \
        ID[m] = (Z)*IS[m]*invA;                                                \
    }                                                                          \
    {   const float alc = -sqrtf((2.0f*lv + 1.0f)/(2.0f*lv));                  \
        RD[lv] = alc*((X)*RS[lv-1] - (Y)*IS[lv-1]);                            \
        ID[lv] = alc*((X)*IS[lv-1] + (Y)*RS[lv-1]);                            \
    }                                                                          \
} while(0)

// ---------------------------------------------------------------------------
// Pass 1: 2 atoms per thread, interleaved value recursions; summed emit;
// single-stage warp reduction (16 partials).
// ---------------------------------------------------------------------------
#define P1_RED(val, idx) do {                                                  \
    float _v = (val);                                                          \
    _v += __shfl_xor_sync(0xffffffffu, _v, 16);                                \
    if (lane < 16) wsh[wloc][lane][idx] = _v;                                  \
} while(0)

#define V_EMIT2(lv, RD1, ID1, RD2, ID2) do {                                   \
    _Pragma("unroll")                                                          \
    for (int m = 0; m <= lv; m++){                                             \
        const float y1 = RD1[m], y2 = RD2[m];                                  \
        _Pragma("unroll")                                                      \
        for (int bb = 0; bb < 3; bb++)                                         \
            P1_RED(f1[bb]*y1 + f2[bb]*y2, vb + bb*49 + lv*7 + (lv-m));         \
    }                                                                          \
    _Pragma("unroll")                                                          \
    for (int m = 1; m <= lv; m++){                                             \
        const float y1 = ID1[m], y2 = ID2[m];                                  \
        _Pragma("unroll")                                                      \
        for (int bb = 0; bb < 3; bb++)                                         \
            P1_RED(f1[bb]*y1 + f2[bb]*y2, vb + bb*49 + (m-1)*7 + lv);          \
    }                                                                          \
} while(0)

__global__ void __launch_bounds__(TPB1) pass1(const float* __restrict__ xyz){
    __shared__ float wsh[2][16][NC];
    const int t    = threadIdx.x;
    const int lane = t & 31;
    const int half = t >> 6;
    const int al   = t & 63;
    const int wloc = al >> 5;
    const int vb   = half*3*49;
    const int j1 = blockIdx.x * APB + al;
    const int j2 = j1 + 64;

    const float x1 = xyz[3*j1+0], y1c = xyz[3*j1+1], z1 = xyz[3*j1+2];
    const float x2 = xyz[3*j2+0], y2c = xyz[3*j2+1], z2 = xyz[3*j2+2];
    const float r21 = x1*x1 + y1c*y1c + z1*z1;
    const float r22 = x2*x2 + y2c*y2c + z2*z2;
    const float d1 = sqrtf(r21), d2 = sqrtf(r22);
    const float tc1 = 1.0f - d1*RCINV, tc2 = 1.0f - d2*RCINV;
    const float rc1 = (d1 < RCF) ? tc1*tc1 : 0.0f;
    const float rc2 = (d2 < RCF) ? tc2*tc2 : 0.0f;

    float f1[3], f2[3];
    {
        const float r61 = r21*r21*r21, r62 = r22*r22*r22;
        f1[0] = rc1 * (half ? r61 : 1.0f);
        f1[1] = f1[0]*r21; f1[2] = f1[1]*r21;
        f2[0] = rc2 * (half ? r62 : 1.0f);
        f2[1] = f2[0]*r22; f2[2] = f2[1]*r22;
    }

    float RA1[LL], IA1[LL], RB1[LL], IB1[LL];
    float RA2[LL], IA2[LL], RB2[LL], IB2[LL];
    RA1[0] = 0.28209479177387814f; IA1[0] = 0.0f;
    RA2[0] = 0.28209479177387814f; IA2[0] = 0.0f;
    V_EMIT2(0, RA1, IA1, RA2, IA2);
    {
        const float sq3 = 1.7320508075688772f;
        const float alc = -1.2247448713915890f;
        RB1[0] = z1*RA1[0]*sq3; IB1[0] = 0.0f;
        RB1[1] = alc*(x1*RA1[0]); IB1[1] = alc*(y1c*RA1[0]);
        RB2[0] = z2*RA2[0]*sq3; IB2[0] = 0.0f;
        RB2[1] = alc*(x2*RA2[0]); IB2[1] = alc*(y2c*RA2[0]);
    }
    V_EMIT2(1, RB1, IB1, RB2, IB2);

    V_STEPG(2, RB1, IB1, RA1, IA1, x1, y1c, z1, r21);
    V_STEPG(2, RB2, IB2, RA2, IA2, x2, y2c, z2, r22);
    V_EMIT2(2, RA1, IA1, RA2, IA2);
    V_STEPG(3, RA1, IA1, RB1, IB1, x1, y1c, z1, r21);
    V_STEPG(3, RA2, IA2, RB2, IB2, x2, y2c, z2, r22);
    V_EMIT2(3, RB1, IB1, RB2, IB2);
    V_STEPG(4, RB1, IB1, RA1, IA1, x1, y1c, z1, r21);
    V_STEPG(4, RB2, IB2, RA2, IA2, x2, y2c, z2, r22);
    V_EMIT2(4, RA1, IA1, RA2, IA2);
    V_STEPG(5, RA1, IA1, RB1, IB1, x1, y1c, z1, r21);
    V_STEPG(5, RA2, IA2, RB2, IB2, x2, y2c, z2, r22);
    V_EMIT2(5, RB1, IB1, RB2, IB2);
    V_STEPG(6, RB1, IB1, RA1, IA1, x1, y1c, z1, r21);
    V_STEPG(6, RB2, IB2, RA2, IA2, x2, y2c, z2, r22);
    V_EMIT2(6, RA1, IA1, RA2, IA2);

    __syncthreads();
    for (int v = t; v < NC; v += TPB1){
        float s = 0.0f;
        #pragma unroll
        for (int w = 0; w < 2; w++)
            #pragma unroll
            for (int c = 0; c < 16; c++)
                s += wsh[w][c][v];
        g_part[blockIdx.x*NC + v] = s;
    }
}

// ---------------------------------------------------------------------------
// Stage-1 reduce: one block per c-channel; 256 threads sum 512 partials.
// ---------------------------------------------------------------------------
__global__ void __launch_bounds__(256) reduce_part(){
    const int v = blockIdx.x;
    const int t = threadIdx.x;
    float s = 0.0f;
    #pragma unroll
    for (int k = 0; k < NBLK1/256; k++)
        s += g_part[(t + k*256)*NC + v];
    s += __shfl_xor_sync(0xffffffffu, s, 16);
    s += __shfl_xor_sync(0xffffffffu, s, 8);
    s += __shfl_xor_sync(0xffffffffu, s, 4);
    s += __shfl_xor_sync(0xffffffffu, s, 2);
    s += __shfl_xor_sync(0xffffffffu, s, 1);
    __shared__ float sm[8];
    if ((t & 31) == 0) sm[t >> 5] = s;
    __syncthreads();
    if (t == 0){
        float r = 0.0f;
        #pragma unroll
        for (int w = 0; w < 8; w++) r += sm[w];
        g_c[v] = r;
    }
}

// ---------------------------------------------------------------------------
// Stage-2: compute p (first 252 outputs) from g_c. One small block.
// ---------------------------------------------------------------------------
__global__ void __launch_bounds__(256) finalize_p(float* __restrict__ out){
    __shared__ float csh[NC];
    const int t = threadIdx.x;
    for (int i = t; i < NC; i += 256) csh[i] = g_c[i];
    __syncthreads();
    if (t < LL*NM*NM){   // 252
        const int l = t / 36;
        const int a = (t / 6) % 6;
        const int b = t % 6;
        const float* ca = &csh[a*49];
        const float* cb = &csh[b*49];
        float s = 0.0f;
        for (int m = 0; m <= l; m++){
            const float w = (m == l) ? 1.0f : 2.0f;
            s += w * ca[l*7 + m] * cb[l*7 + m];
        }
        for (int lp = 0; lp < l; lp++){
            s += 2.0f * ca[lp*7 + l] * cb[lp*7 + l];
        }
        out[t] = s;
    }
}

// ---------------------------------------------------------------------------
// Pass 2 (R14 form): values-only ping-pong recursion; gradients synthesized
// from row l-1; single-buffer smem staging -> cp.async.bulk stores.
// Grid doubled by l-split: group 0 emits l in {0,5,6}; group 1 l in {1,2,3,4}.
// ---------------------------------------------------------------------------
__device__ __forceinline__ int pair_idx(int a, int b){
    return a*6 - (a*(a+1))/2 + b;
}

#define LGRP(lv) ((lv)==0 || (lv)==5 || (lv)==6 ? 0 : 1)

#define V_STEP(lv, RS, IS, RD, ID) V_STEPG(lv, RS, IS, RD, ID, x, y, z, r2)

#define D_EMIT(lv, CR, CI, PR, PI) if (grp == LGRP(lv)) {                      \
    float G[6]={0,0,0,0,0,0}, Hx[6]={0,0,0,0,0,0},                             \
          Hy[6]={0,0,0,0,0,0}, Hz[6]={0,0,0,0,0,0};                            \
    _Pragma("unroll")                                                          \
    for (int m = 0; m <= lv; m++){                                             \
        const float az  = (m <= lv-1)                                          \
            ? sqrtf((float)((lv-m)*(lv+m))*(2.0f*lv+1.0f)/(2.0f*lv-1.0f))      \
            : 0.0f;                                                            \
        const float apH = (m+1 <= lv-1)                                        \
            ? 0.5f*sqrtf((float)((lv-m)*(lv-m-1))*(2.0f*lv+1.0f)/(2.0f*lv-1.0f))\
            : 0.0f;                                                            \
        const float amH = (lv >= 1 && (m >= 1 || lv >= 2))                     \
            ? 0.5f*sqrtf((float)((lv+m)*(lv+m-1))*(2.0f*lv+1.0f)/(2.0f*lv-1.0f))\
            : 0.0f;                                                            \
        const float prp = (m+1 <= lv-1) ? PR[m+1] : 0.0f;                      \
        const float pip = (m+1 <= lv-1) ? PI[m+1] : 0.0f;                      \
        const float prm = (m >= 1) ? PR[m-1] : ((lv >= 2) ? -PR[1] : 0.0f);    \
        const float pim = (m >= 1) ? PI[m-1] : ((lv >= 2) ?  PI[1] : 0.0f);    \
        const float pzr = (m <= lv-1) ? PR[m] : 0.0f;                          \
        const float pzi = (m <= lv-1) ? PI[m] : 0.0f;                          \
        const float gzr = az*pzr,                 gzi = az*pzi;                \
        const float gxr = apH*prp - amH*prm,      gxi = apH*pip - amH*pim;     \
        const float gyr = apH*pip + amH*pim,      gyi = -(apH*prp + amH*prm);  \
        const float w = (m == 0) ? 1.0f : 2.0f;                                \
        _Pragma("unroll")                                                      \
        for (int b = 0; b < 6; b++){                                           \
            const float wr = w * csh[b*49 + lv*7 + (lv - m)];                  \
            G[b]  += wr*CR[m]; Hx[b] += wr*gxr;                                \
            Hy[b] += wr*gyr;   Hz[b] += wr*gzr;                                \
        }                                                                      \
        if (m >= 1){                                                           \
            _Pragma("unroll")                                                  \
            for (int b = 0; b < 6; b++){                                       \
                const float wi = 2.0f * csh[b*49 + (m-1)*7 + lv];              \
                G[b]  += wi*CI[m]; Hx[b] += wi*gxi;                            \
                Hy[b] += wi*gyi;   Hz[b] += wi*gzi;                            \
            }                                                                  \
        }                                                                      \
    }                                                                          \
    /* wait for previous l's bulk copies (smem reads) before re-staging */     \
    if (t < 36)                                                                \
        asm volatile("cp.async.bulk.wait_group.read 0;" ::: "memory");         \
    __syncthreads();                                                           \
    /* stage 21 unique pairs into shared */                                    \
    float pa = 1.0f;                                                           \
    _Pragma("unroll")                                                          \
    for (int a = 0; a < 6; a++){                                               \
        const float fa  = rcut*pa;                                             \
        const float dca = pa*(drc + (2.0f*a)*rcut*invd);                       \
        float pb = pa;                                                         \
        _Pragma("unroll")                                                      \
        for (int b = a; b < 6; b++){                                           \
            const float fb  = rcut*pb;                                         \
            const float dcb = pb*(drc + (2.0f*b)*rcut*invd);                   \
            const float s  = dca*G[b] + dcb*G[a];                              \
            float* sp = &stage[pair_idx(a,b)][3*t];                            \
            sp[0] = ux*s + fa*Hx[b] + fb*Hx[a];                                \
            sp[1] = uy*s + fa*Hy[b] + fb*Hy[a];                                \
            sp[2] = uz*s + fa*Hz[b] + fb*Hz[a];                                \
            pb *= r2;                                                          \
        }                                                                      \
        pa *= r2;                                                              \
    }                                                                          \
    __syncthreads();                                                           \
    /* one async bulk copy per output stream (1536 B contiguous) */            \
    if (t < 36){                                                               \
        asm volatile("fence.proxy.async.shared::cta;" ::: "memory");           \
        const int a = t / 6, b2 = t % 6;                                       \
        const int p = (a <= b2) ? pair_idx(a,b2) : pair_idx(b2,a);             \
        const unsigned src = stage_u32 + (unsigned)(p*(TPB2*3*4));             \
        float* dst = out + 252 + (size_t)(lv*36 + t)*stride                    \
                   + (size_t)ablk*(TPB2*3);                                    \
        asm volatile(                                                          \
            "cp.async.bulk.global.shared::cta.bulk_group [%0], [%1], %2;"      \
            :: "l"(dst), "r"(src), "n"(TPB2*3*4) : "memory");                  \
        asm volatile("cp.async.bulk.commit_group;" ::: "memory");              \
    }                                                                          \
}

__global__ void __launch_bounds__(TPB2, 5) pass2(const float* __restrict__ xyz,
                                                 float* __restrict__ out){
    __shared__ __align__(16) float stage[21][TPB2*3];
    __shared__ float csh[NC];
    const int t = threadIdx.x;
    const int grp  = blockIdx.x >> 9;          // 0: l in {0,5,6}; 1: l in {1,2,3,4}
    const int ablk = blockIdx.x & (NBLK2-1);   // atom block
    const unsigned stage_u32 = (unsigned)__cvta_generic_to_shared(stage);
    for (int i = t; i < NC; i += TPB2) csh[i] = g_c[i];
    __syncthreads();

    const int j = ablk * TPB2 + t;
    const float x = xyz[3*j+0], y = xyz[3*j+1], z = xyz[3*j+2];
    const float r2 = x*x + y*y + z*z;
    const float invd = rsqrtf(r2);
    const float d = r2 * invd;
    const float ux = x*invd, uy = y*invd, uz = z*invd;

    const float tc = 1.0f - d*RCINV;
    const bool  in = (d < RCF);
    const float rcut = in ? tc*tc : 0.0f;
    const float drc  = in ? (-2.0f*RCINV)*tc : 0.0f;

    const size_t stride = (size_t)3 * NATOMS;

    float RA[LL], IA[LL], RB[LL], IB[LL];
    RA[0] = 0.28209479177387814f; IA[0] = 0.0f;
    D_EMIT(0, RA, IA, RB, IB);

    {
        const float sq3 = 1.7320508075688772f;
        RB[0] = z*RA[0]*sq3;
        IB[0] = 0.0f;
        const float alc = -1.2247448713915890f;
        RB[1] = alc*(x*RA[0]);
        IB[1] = alc*(y*RA[0]);
    }
    D_EMIT(1, RB, IB, RA, IA);

    V_STEP(2, RB, IB, RA, IA); D_EMIT(2, RA, IA, RB, IB);
    V_STEP(3, RA, IA, RB, IB); D_EMIT(3, RB, IB, RA, IA);
    V_STEP(4, RB, IB, RA, IA); D_EMIT(4, RA, IA, RB, IB);
    V_STEP(5, RA, IA, RB, IB); D_EMIT(5, RB, IB, RA, IA);
    V_STEP(6, RB, IB, RA, IA); D_EMIT(6, RA, IA, RB, IB);

    // drain outstanding bulk-store groups before exit
    if (t < 36)
        asm volatile("cp.async.bulk.wait_group 0;" ::: "memory");
}

// ---------------------------------------------------------------------------
extern "C" void kernel_launch(void* const* d_in, const int* in_sizes, int n_in,
                              void* d_out, int out_size){
    const float* xyz = (const float*)d_in[0];
    float* out = (float*)d_out;
    pass1<<<NBLK1, TPB1>>>(xyz);
    reduce_part<<<NC, 256>>>();
    finalize_p<<<1, 256>>>(out);
    pass2<<<2*NBLK2, TPB2>>>(xyz, out);
}